// round 1
// baseline (speedup 1.0000x reference)
#include <cuda_runtime.h>
#include <math.h>

// AtlasMultiDiffAttn: fully fused, one block per batch element.
// x[b] (56x128) -> smem; conv1(silu) -> h1 (transposed in smem) ->
// conv2(silu)+mean -> q -> LN -> k-proj from smem x + LN + logits ->
// softmax -> differential combine -> softmax -> head mean -> out[b,56].

#define BB 8192
#define AA 56
#define EE 128
#define HDD 16
#define NH2 8
#define NHH 4
#define XS_PITCH 134   // e in [-3,130] halo, zero-padded
#define H1_PITCH 71    // a in [-3,67] halo, zero-padded, odd pitch = conflict-free

__device__ float g_wkT[EE * EE];  // w_k transposed: [e][o]

__global__ void transpose_wk_kernel(const float* __restrict__ wk) {
    int idx = blockIdx.x * blockDim.x + threadIdx.x;
    if (idx < EE * EE) {
        int o = idx >> 7, e = idx & 127;
        g_wkT[e * EE + o] = wk[o * EE + e];
    }
}

__device__ __forceinline__ float silu_f(float v) {
    return v / (1.f + expf(-v));
}

__global__ __launch_bounds__(256, 3)
void atlas_fused_kernel(const float* __restrict__ x,
                        const float* __restrict__ w_emb,
                        const float* __restrict__ b_emb,
                        const float* __restrict__ w_atlas,
                        const float* __restrict__ b_atlas,
                        const float* __restrict__ qn_w, const float* __restrict__ qn_b,
                        const float* __restrict__ kn_w, const float* __restrict__ kn_b,
                        const float* __restrict__ lq1, const float* __restrict__ lk1,
                        const float* __restrict__ lq2, const float* __restrict__ lk2,
                        float* __restrict__ out)
{
    extern __shared__ float sm[];
    float* xs     = sm;                       // 56*134
    float* h1s    = xs + AA * XS_PITCH;       // 128*71
    float* qsm    = h1s + EE * H1_PITCH;      // 128
    float* qnsm   = qsm + EE;                 // 128
    float* logits = qnsm + EE;                // 8*56
    float* attn   = logits + NH2 * AA;        // 8*56
    float* p2     = attn + NH2 * AA;          // 4*56
    float* lamp   = p2 + NHH * AA;            // 1

    const int tid  = threadIdx.x;
    const int warp = tid >> 5;
    const int lane = tid & 31;
    const int b    = blockIdx.x;

    // ---- zero xs + h1s (covers all halos), compute lambda ----
    const int ZN = AA * XS_PITCH + EE * H1_PITCH;
    for (int i = tid; i < ZN; i += 256) sm[i] = 0.f;
    if (tid == 0) {
        float s1 = 0.f, s2 = 0.f;
        #pragma unroll
        for (int d = 0; d < HDD; d++) { s1 += lq1[d] * lk1[d]; s2 += lq2[d] * lk2[d]; }
        *lamp = expf(s1) - expf(s2) + 0.7f;
    }
    __syncthreads();

    // ---- load x[b] into xs (with halo offset +3 along e) ----
    const float4* xb4 = (const float4*)(x + (size_t)b * (AA * EE));
    for (int i4 = tid; i4 < (AA * EE) / 4; i4 += 256) {
        float4 v = xb4[i4];
        int idx = i4 * 4;
        int a = idx >> 7, e = idx & 127;
        float* p = xs + a * XS_PITCH + e + 3;
        p[0] = v.x; p[1] = v.y; p[2] = v.z; p[3] = v.w;
    }
    __syncthreads();

    // ---- conv1 over e (channels = a), + silu; store transposed h1s[e][a+3] ----
    {
        const int o0 = warp * 7;   // 8 warps x 7 outputs = 56
        float acc[7][4];
        #pragma unroll
        for (int g = 0; g < 7; g++) {
            float bv = b_emb[o0 + g];
            #pragma unroll
            for (int c = 0; c < 4; c++) acc[g][c] = bv;
        }
        for (int i = 0; i < AA; i++) {
            const float* xrow = xs + i * XS_PITCH + lane;
            const float* wp   = w_emb + (o0 * AA + i) * 7;
            #pragma unroll
            for (int t = 0; t < 7; t++) {
                float x0 = xrow[t];
                float x1 = xrow[32 + t];
                float x2 = xrow[64 + t];
                float x3 = xrow[96 + t];
                #pragma unroll
                for (int g = 0; g < 7; g++) {
                    float w = wp[g * (AA * 7) + t];
                    acc[g][0] += w * x0; acc[g][1] += w * x1;
                    acc[g][2] += w * x2; acc[g][3] += w * x3;
                }
            }
        }
        #pragma unroll
        for (int g = 0; g < 7; g++) {
            #pragma unroll
            for (int c = 0; c < 4; c++) {
                float v = silu_f(acc[g][c]);
                h1s[(lane + 32 * c) * H1_PITCH + (o0 + g + 3)] = v;
            }
        }
    }
    __syncthreads();

    // ---- conv2 over a (channels = e), + silu + mean over a -> qsm[128] ----
    {
        const int a0 = lane, a1 = lane + 32;
        #pragma unroll 1
        for (int grp = 0; grp < 4; grp++) {
            const int og = warp * 16 + grp * 4;
            float acc0[4], acc1[4];
            #pragma unroll
            for (int g = 0; g < 4; g++) {
                float bv = b_atlas[og + g];
                acc0[g] = bv; acc1[g] = bv;
            }
            for (int i = 0; i < EE; i++) {
                const float* hrow = h1s + i * H1_PITCH;
                const float* wp   = w_atlas + (og * EE + i) * 7;
                #pragma unroll
                for (int t = 0; t < 7; t++) {
                    float x0 = hrow[a0 + t];
                    float x1 = hrow[a1 + t];   // lanes>=24: reads zeros, masked later
                    #pragma unroll
                    for (int g = 0; g < 4; g++) {
                        float w = wp[g * (EE * 7) + t];
                        acc0[g] += w * x0; acc1[g] += w * x1;
                    }
                }
            }
            #pragma unroll
            for (int g = 0; g < 4; g++) {
                float v0 = silu_f(acc0[g]);
                float v1 = 0.f;
                if (lane < 24) v1 = silu_f(acc1[g]);
                float s = v0 + v1;
                #pragma unroll
                for (int off = 16; off > 0; off >>= 1)
                    s += __shfl_xor_sync(0xffffffffu, s, off);
                if (lane == 0) qsm[og + g] = s * (1.f / 56.f);
            }
        }
    }
    __syncthreads();

    // ---- q layernorm per head (16) + scaling 0.25 ----
    if (tid < EE) {
        float v = qsm[tid];
        float s = v, ss = v * v;
        #pragma unroll
        for (int off = 8; off > 0; off >>= 1) {
            s  += __shfl_xor_sync(0xffffffffu, s,  off);
            ss += __shfl_xor_sync(0xffffffffu, ss, off);
        }
        float m   = s * (1.f / 16.f);
        float var = ss * (1.f / 16.f) - m * m;
        int d = tid & 15;
        float qn = (v - m) * rsqrtf(var + 1e-5f) * qn_w[d] + qn_b[d];
        qnsm[tid] = qn * 0.25f;
    }
    __syncthreads();

    // ---- k projection + k layernorm + logits ----
    {
        const int d   = lane & 15;
        const float knw = kn_w[d], knb = kn_b[d];
        for (int j = 0; j < 7; j++) {
            const int l = warp + 8 * j;     // 8 warps x 7 = 56 positions
            float acc[4] = {0.f, 0.f, 0.f, 0.f};
            const float* xrow = xs + l * XS_PITCH + 3;
            for (int e = 0; e < EE; e++) {
                float xv = xrow[e];                   // warp-uniform broadcast
                const float* wrow = g_wkT + e * EE + lane;
                acc[0] += wrow[0]  * xv;
                acc[1] += wrow[32] * xv;
                acc[2] += wrow[64] * xv;
                acc[3] += wrow[96] * xv;
            }
            #pragma unroll
            for (int c = 0; c < 4; c++) {
                float v = acc[c];
                float s = v, ss = v * v;
                #pragma unroll
                for (int off = 8; off > 0; off >>= 1) {
                    s  += __shfl_xor_sync(0xffffffffu, s,  off);
                    ss += __shfl_xor_sync(0xffffffffu, ss, off);
                }
                float m   = s * (1.f / 16.f);
                float var = ss * (1.f / 16.f) - m * m;
                float kn  = (v - m) * rsqrtf(var + 1e-5f) * knw + knb;
                float part = kn * qnsm[lane + 32 * c];
                #pragma unroll
                for (int off = 8; off > 0; off >>= 1)
                    part += __shfl_xor_sync(0xffffffffu, part, off);
                int h2 = 2 * c + (lane >> 4);
                if (d == 0) logits[h2 * AA + l] = part;
            }
        }
    }
    __syncthreads();

    // ---- softmax over A per (h2) row: 8 warps, one row each ----
    {
        const int h2 = warp;
        float v0 = logits[h2 * AA + lane];
        float v1 = (lane < 24) ? logits[h2 * AA + 32 + lane] : -INFINITY;
        float mx = fmaxf(v0, v1);
        #pragma unroll
        for (int off = 16; off > 0; off >>= 1)
            mx = fmaxf(mx, __shfl_xor_sync(0xffffffffu, mx, off));
        float e0 = expf(v0 - mx);
        float e1 = (lane < 24) ? expf(v1 - mx) : 0.f;
        float s = e0 + e1;
        #pragma unroll
        for (int off = 16; off > 0; off >>= 1)
            s += __shfl_xor_sync(0xffffffffu, s, off);
        float inv = 1.f / s;
        attn[h2 * AA + lane] = e0 * inv;
        if (lane < 24) attn[h2 * AA + 32 + lane] = e1 * inv;
    }
    __syncthreads();

    // ---- differential combine + second softmax: warps 0..3 ----
    if (warp < NHH) {
        const int h = warp;
        const float lam = *lamp;
        float v0 = attn[(2 * h) * AA + lane] - lam * attn[(2 * h + 1) * AA + lane];
        float v1 = (lane < 24)
                 ? attn[(2 * h) * AA + 32 + lane] - lam * attn[(2 * h + 1) * AA + 32 + lane]
                 : -INFINITY;
        float mx = fmaxf(v0, v1);
        #pragma unroll
        for (int off = 16; off > 0; off >>= 1)
            mx = fmaxf(mx, __shfl_xor_sync(0xffffffffu, mx, off));
        float e0 = expf(v0 - mx);
        float e1 = (lane < 24) ? expf(v1 - mx) : 0.f;
        float s = e0 + e1;
        #pragma unroll
        for (int off = 16; off > 0; off >>= 1)
            s += __shfl_xor_sync(0xffffffffu, s, off);
        float inv = 1.f / s;
        p2[h * AA + lane] = e0 * inv;
        if (lane < 24) p2[h * AA + 32 + lane] = e1 * inv;
    }
    __syncthreads();

    // ---- mean over heads, write out ----
    if (tid < AA) {
        float o = 0.25f * (p2[tid] + p2[AA + tid] + p2[2 * AA + tid] + p2[3 * AA + tid]);
        out[(size_t)b * AA + tid] = o;
    }
}

static const int SMEM_BYTES =
    (AA * XS_PITCH + EE * H1_PITCH + EE + EE + NH2 * AA + NH2 * AA + NHH * AA + 4) * 4;

extern "C" void kernel_launch(void* const* d_in, const int* in_sizes, int n_in,
                              void* d_out, int out_size) {
    const float* x       = (const float*)d_in[0];
    const float* w_emb   = (const float*)d_in[1];
    const float* b_emb   = (const float*)d_in[2];
    const float* w_atlas = (const float*)d_in[3];
    const float* b_atlas = (const float*)d_in[4];
    const float* w_k     = (const float*)d_in[5];
    const float* qn_w    = (const float*)d_in[6];
    const float* qn_b    = (const float*)d_in[7];
    const float* kn_w    = (const float*)d_in[8];
    const float* kn_b    = (const float*)d_in[9];
    const float* lq1     = (const float*)d_in[10];
    const float* lk1     = (const float*)d_in[11];
    const float* lq2     = (const float*)d_in[12];
    const float* lk2     = (const float*)d_in[13];
    float* out = (float*)d_out;

    cudaFuncSetAttribute(atlas_fused_kernel,
                         cudaFuncAttributeMaxDynamicSharedMemorySize, SMEM_BYTES);

    transpose_wk_kernel<<<64, 256>>>(w_k);
    atlas_fused_kernel<<<BB, 256, SMEM_BYTES>>>(
        x, w_emb, b_emb, w_atlas, b_atlas,
        qn_w, qn_b, kn_w, kn_b, lq1, lk1, lq2, lk2, out);
}

// round 2
// speedup vs baseline: 1.5135x; 1.5135x over previous
#include <cuda_runtime.h>
#include <math.h>

#define AA 56
#define EE 128
#define XP 134      // e-slot pitch per a-row (float2 slots), e' = e+3 in [0,133]
#define HP 71       // a-slot pitch per i-row (float2 slots), odd => conflict-free

typedef unsigned long long ull;

// packed weights (prep kernel fills these)
__device__ float g_w1p[8 * 56 * 56];     // [slice8][i56][g*8+t], t<7,g<7 else 0
__device__ float g_w2p[32 * 128 * 32];   // [slice32][i128][g*8+t], t<7 else 0
__device__ float g_wkT[128 * 128];       // [e][o]

__global__ void prep_kernel(const float* __restrict__ w_emb,
                            const float* __restrict__ w_atlas,
                            const float* __restrict__ w_k) {
    int idx = blockIdx.x * blockDim.x + threadIdx.x;
    if (idx < 8 * 56 * 56) {
        int s = idx / (56 * 56); int r = idx % (56 * 56);
        int i = r / 56; int gt = r % 56;
        int g = gt >> 3, t = gt & 7;
        float v = 0.f;
        if (t < 7 && g < 7) v = w_emb[(((s * 7 + g) * 56) + i) * 7 + t];
        g_w1p[idx] = v;
    }
    if (idx < 32 * 128 * 32) {
        int s = idx / (128 * 32); int r = idx % (128 * 32);
        int i = r >> 5; int gt = r & 31;
        int g = gt >> 3, t = gt & 7;
        g_w2p[idx] = (t < 7) ? w_atlas[(((s * 4 + g) * 128) + i) * 7 + t] : 0.f;
    }
    if (idx < 128 * 128) {
        int o = idx >> 7, e = idx & 127;
        g_wkT[e * 128 + o] = w_k[idx];
    }
}

__device__ __forceinline__ ull packf2(float v) {
    ull r; asm("mov.b64 %0,{%1,%1};" : "=l"(r) : "f"(v)); return r;
}
__device__ __forceinline__ ull pack2(float a, float b) {
    ull r; asm("mov.b64 %0,{%1,%2};" : "=l"(r) : "f"(a), "f"(b)); return r;
}
__device__ __forceinline__ void up2(ull v, float& a, float& b) {
    asm("mov.b64 {%0,%1},%2;" : "=f"(a), "=f"(b) : "l"(v));
}
__device__ __forceinline__ void fma2(ull& d, ull a, ull b) {
    asm("fma.rn.f32x2 %0,%1,%2,%0;" : "+l"(d) : "l"(a), "l"(b));
}
__device__ __forceinline__ float silu_f(float v) {
    return v / (1.f + __expf(-v));
}

__global__ __launch_bounds__(256, 1)
void atlas2_kernel(const float* __restrict__ x,
                   const float* __restrict__ b_emb,
                   const float* __restrict__ b_atlas,
                   const float* __restrict__ qn_w, const float* __restrict__ qn_b,
                   const float* __restrict__ kn_w, const float* __restrict__ kn_b,
                   const float* __restrict__ lq1, const float* __restrict__ lk1,
                   const float* __restrict__ lq2, const float* __restrict__ lk2,
                   float* __restrict__ out)
{
    extern __shared__ float sm[];
    ull*   xsu   = (ull*)sm;                    // [56*134] item-pairs of x
    ull*   h1u   = xsu + AA * XP;               // [128*71] item-pairs of h1
    float* qs    = (float*)(h1u + EE * HP);     // [2][128]
    float* qn    = qs + 256;                    // [2][128]
    float* logits= qn + 256;                    // [2][8][56]
    float* attn  = logits + 2 * 8 * 56;         // [2][8][56]
    float* p2    = attn + 2 * 8 * 56;           // [2][4][56]
    float* lamp  = p2 + 2 * 4 * 56;

    const int tid = threadIdx.x, warp = tid >> 5, lane = tid & 31;
    const int bp = blockIdx.x;                  // pair index: items 2bp, 2bp+1

    // ---- zero pair buffers (halos), lambda ----
    {
        const int ZN = AA * XP + EE * HP;
        for (int i = tid; i < ZN; i += 256) xsu[i] = 0ULL;
    }
    if (tid == 0) {
        float s1 = 0.f, s2 = 0.f;
        #pragma unroll
        for (int d = 0; d < 16; d++) { s1 += lq1[d] * lk1[d]; s2 += lq2[d] * lk2[d]; }
        *lamp = __expf(s1) - __expf(s2) + 0.7f;
    }
    __syncthreads();

    // ---- load both items of x, interleaved as float2 pairs ----
    {
        const float4* x0 = (const float4*)(x + (size_t)(2 * bp) * AA * EE);
        const float4* x1 = (const float4*)(x + (size_t)(2 * bp + 1) * AA * EE);
        for (int q = tid; q < AA * EE / 4; q += 256) {
            float4 a = x0[q], b = x1[q];
            int base = q * 4; int ar = base >> 7, e0 = base & 127;
            ull* dst = xsu + ar * XP + e0 + 3;
            dst[0] = pack2(a.x, b.x); dst[1] = pack2(a.y, b.y);
            dst[2] = pack2(a.z, b.z); dst[3] = pack2(a.w, b.w);
        }
    }
    __syncthreads();

    // ---- conv1 (channels=a, conv over e) + silu -> h1 pairs (transposed) ----
    {
        ull acc[7][4];
        #pragma unroll
        for (int g = 0; g < 7; g++) {
            ull b2 = packf2(b_emb[warp * 7 + g]);
            acc[g][0] = b2; acc[g][1] = b2; acc[g][2] = b2; acc[g][3] = b2;
        }
        for (int i = 0; i < AA; i++) {
            const ull* xrow = xsu + i * XP + lane;
            const float4* wrow = (const float4*)(g_w1p + (warp * 56 + i) * 56);
            ull xv[4][4];
            #pragma unroll
            for (int t = 0; t < 4; t++)
                #pragma unroll
                for (int c = 0; c < 4; c++) xv[t][c] = xrow[t + 32 * c];
            #pragma unroll
            for (int g = 0; g < 7; g++) {
                float4 wq = wrow[g * 2];
                ull w0 = packf2(wq.x), w1 = packf2(wq.y), w2 = packf2(wq.z), w3 = packf2(wq.w);
                #pragma unroll
                for (int c = 0; c < 4; c++) {
                    fma2(acc[g][c], w0, xv[0][c]); fma2(acc[g][c], w1, xv[1][c]);
                    fma2(acc[g][c], w2, xv[2][c]); fma2(acc[g][c], w3, xv[3][c]);
                }
            }
            #pragma unroll
            for (int t = 0; t < 3; t++)
                #pragma unroll
                for (int c = 0; c < 4; c++) xv[t][c] = xrow[4 + t + 32 * c];
            #pragma unroll
            for (int g = 0; g < 7; g++) {
                float4 wq = wrow[g * 2 + 1];
                ull w0 = packf2(wq.x), w1 = packf2(wq.y), w2 = packf2(wq.z);
                #pragma unroll
                for (int c = 0; c < 4; c++) {
                    fma2(acc[g][c], w0, xv[0][c]); fma2(acc[g][c], w1, xv[1][c]);
                    fma2(acc[g][c], w2, xv[2][c]);
                }
            }
        }
        #pragma unroll
        for (int g = 0; g < 7; g++)
            #pragma unroll
            for (int c = 0; c < 4; c++) {
                float v0, v1; up2(acc[g][c], v0, v1);
                float2 s = make_float2(silu_f(v0), silu_f(v1));
                *(float2*)&h1u[(lane + 32 * c) * HP + (warp * 7 + g + 3)] = s;
            }
    }
    __syncthreads();

    // ---- conv2 (channels=e, conv over a) + silu + mean over a -> qs[2][128] ----
    {
        #pragma unroll 1
        for (int grp = 0; grp < 4; grp++) {
            const int og = warp * 16 + grp * 4;
            ull acc[4][2];
            #pragma unroll
            for (int g = 0; g < 4; g++) {
                ull b2 = packf2(b_atlas[og + g]);
                acc[g][0] = b2; acc[g][1] = b2;
            }
            for (int i = 0; i < EE; i++) {
                const ull* hrow = h1u + i * HP + lane;
                ull hv[7][2];
                #pragma unroll
                for (int t = 0; t < 7; t++) { hv[t][0] = hrow[t]; hv[t][1] = hrow[32 + t]; }
                const float4* wr = (const float4*)(g_w2p + ((warp * 4 + grp) * 128 + i) * 32);
                #pragma unroll
                for (int g = 0; g < 4; g++) {
                    float4 wa = wr[g * 2], wb = wr[g * 2 + 1];
                    ull w0 = packf2(wa.x), w1 = packf2(wa.y), w2 = packf2(wa.z), w3 = packf2(wa.w);
                    ull w4 = packf2(wb.x), w5 = packf2(wb.y), w6 = packf2(wb.z);
                    fma2(acc[g][0], w0, hv[0][0]); fma2(acc[g][1], w0, hv[0][1]);
                    fma2(acc[g][0], w1, hv[1][0]); fma2(acc[g][1], w1, hv[1][1]);
                    fma2(acc[g][0], w2, hv[2][0]); fma2(acc[g][1], w2, hv[2][1]);
                    fma2(acc[g][0], w3, hv[3][0]); fma2(acc[g][1], w3, hv[3][1]);
                    fma2(acc[g][0], w4, hv[4][0]); fma2(acc[g][1], w4, hv[4][1]);
                    fma2(acc[g][0], w5, hv[5][0]); fma2(acc[g][1], w5, hv[5][1]);
                    fma2(acc[g][0], w6, hv[6][0]); fma2(acc[g][1], w6, hv[6][1]);
                }
            }
            #pragma unroll
            for (int g = 0; g < 4; g++) {
                float a0, a1, b0, b1;
                up2(acc[g][0], a0, a1); up2(acc[g][1], b0, b1);
                float s0 = silu_f(a0) + ((lane < 24) ? silu_f(b0) : 0.f);
                float s1 = silu_f(a1) + ((lane < 24) ? silu_f(b1) : 0.f);
                #pragma unroll
                for (int off = 16; off > 0; off >>= 1) {
                    s0 += __shfl_xor_sync(0xffffffffu, s0, off);
                    s1 += __shfl_xor_sync(0xffffffffu, s1, off);
                }
                if (lane == 0) { qs[og + g] = s0 * (1.f / 56.f); qs[128 + og + g] = s1 * (1.f / 56.f); }
            }
        }
    }
    __syncthreads();

    // ---- q layernorm per head (16) + 0.25 scaling ----
    {
        int it = tid >> 7, idx = tid & 127;
        float v = qs[it * 128 + idx];
        float s = v, ss = v * v;
        #pragma unroll
        for (int off = 8; off > 0; off >>= 1) {
            s  += __shfl_xor_sync(0xffffffffu, s,  off);
            ss += __shfl_xor_sync(0xffffffffu, ss, off);
        }
        float m = s * (1.f / 16.f);
        float var = ss * (1.f / 16.f) - m * m;
        int d = idx & 15;
        qn[it * 128 + idx] = ((v - m) * rsqrtf(var + 1e-5f) * qn_w[d] + qn_b[d]) * 0.25f;
    }
    __syncthreads();

    // ---- k projection + k layernorm + logits ----
    {
        ull acc[7][4];
        #pragma unroll
        for (int j = 0; j < 7; j++)
            #pragma unroll
            for (int q = 0; q < 4; q++) acc[j][q] = 0ULL;
        const int p0 = warp * 7;
        for (int e = 0; e < EE; e++) {
            float4 wq = *(const float4*)(g_wkT + e * 128 + lane * 4);
            ull w0 = packf2(wq.x), w1 = packf2(wq.y), w2 = packf2(wq.z), w3 = packf2(wq.w);
            const ull* xcol = xsu + e + 3;
            #pragma unroll
            for (int j = 0; j < 7; j++) {
                ull xv = xcol[(p0 + j) * XP];
                fma2(acc[j][0], w0, xv); fma2(acc[j][1], w1, xv);
                fma2(acc[j][2], w2, xv); fma2(acc[j][3], w3, xv);
            }
        }
        float4 qv0 = *(float4*)&qn[lane * 4];
        float4 qv1 = *(float4*)&qn[128 + lane * 4];
        float4 kw = *(const float4*)(kn_w + (lane & 3) * 4);
        float4 kb = *(const float4*)(kn_b + (lane & 3) * 4);
        #pragma unroll
        for (int j = 0; j < 7; j++) {
            float k0[4], k1[4];
            #pragma unroll
            for (int q = 0; q < 4; q++) up2(acc[j][q], k0[q], k1[q]);
            #pragma unroll
            for (int it = 0; it < 2; it++) {
                float* kv = it ? k1 : k0;
                float s = kv[0] + kv[1] + kv[2] + kv[3];
                float ss = kv[0]*kv[0] + kv[1]*kv[1] + kv[2]*kv[2] + kv[3]*kv[3];
                s  += __shfl_xor_sync(0xffffffffu, s, 1);  s  += __shfl_xor_sync(0xffffffffu, s, 2);
                ss += __shfl_xor_sync(0xffffffffu, ss, 1); ss += __shfl_xor_sync(0xffffffffu, ss, 2);
                float m = s * (1.f / 16.f);
                float var = ss * (1.f / 16.f) - m * m;
                float inv = rsqrtf(var + 1e-5f);
                float4 qv = it ? qv1 : qv0;
                float lp = ((kv[0] - m) * inv * kw.x + kb.x) * qv.x
                         + ((kv[1] - m) * inv * kw.y + kb.y) * qv.y
                         + ((kv[2] - m) * inv * kw.z + kb.z) * qv.z
                         + ((kv[3] - m) * inv * kw.w + kb.w) * qv.w;
                lp += __shfl_xor_sync(0xffffffffu, lp, 1);
                lp += __shfl_xor_sync(0xffffffffu, lp, 2);
                if ((lane & 3) == 0) logits[it * 448 + (lane >> 2) * 56 + p0 + j] = lp;
            }
        }
    }
    __syncthreads();

    // ---- softmax over A per (item, h2): 8 warps x 2 items ----
    #pragma unroll
    for (int it = 0; it < 2; it++) {
        const float* row = logits + it * 448 + warp * 56;
        float v0 = row[lane];
        float v1 = (lane < 24) ? row[32 + lane] : -1e30f;
        float mx = fmaxf(v0, v1);
        #pragma unroll
        for (int off = 16; off > 0; off >>= 1)
            mx = fmaxf(mx, __shfl_xor_sync(0xffffffffu, mx, off));
        float e0 = __expf(v0 - mx);
        float e1 = (lane < 24) ? __expf(v1 - mx) : 0.f;
        float s = e0 + e1;
        #pragma unroll
        for (int off = 16; off > 0; off >>= 1)
            s += __shfl_xor_sync(0xffffffffu, s, off);
        float inv = 1.f / s;
        float* arow = attn + it * 448 + warp * 56;
        arow[lane] = e0 * inv;
        if (lane < 24) arow[32 + lane] = e1 * inv;
    }
    __syncthreads();

    // ---- differential combine + second softmax: warp w -> (it=w>>2, h=w&3) ----
    {
        const int it = warp >> 2, h = warp & 3;
        const float lam = *lamp;
        const float* a0r = attn + it * 448 + (2 * h) * 56;
        const float* a1r = attn + it * 448 + (2 * h + 1) * 56;
        float v0 = a0r[lane] - lam * a1r[lane];
        float v1 = (lane < 24) ? (a0r[32 + lane] - lam * a1r[32 + lane]) : -1e30f;
        float mx = fmaxf(v0, v1);
        #pragma unroll
        for (int off = 16; off > 0; off >>= 1)
            mx = fmaxf(mx, __shfl_xor_sync(0xffffffffu, mx, off));
        float e0 = __expf(v0 - mx);
        float e1 = (lane < 24) ? __expf(v1 - mx) : 0.f;
        float s = e0 + e1;
        #pragma unroll
        for (int off = 16; off > 0; off >>= 1)
            s += __shfl_xor_sync(0xffffffffu, s, off);
        float inv = 1.f / s;
        float* prow = p2 + it * 224 + h * 56;
        prow[lane] = e0 * inv;
        if (lane < 24) prow[32 + lane] = e1 * inv;
    }
    __syncthreads();

    // ---- mean over heads, write both items ----
    if (tid < 112) {
        int it = tid / 56, a = tid - it * 56;
        const float* base = p2 + it * 224;
        out[(size_t)(2 * bp + it) * 56 + a] =
            0.25f * (base[a] + base[56 + a] + base[112 + a] + base[168 + a]);
    }
}

static const int SMEM_BYTES =
    (AA * XP + EE * HP) * 8 + (256 + 256 + 896 + 896 + 448 + 4) * 4;

extern "C" void kernel_launch(void* const* d_in, const int* in_sizes, int n_in,
                              void* d_out, int out_size) {
    const float* x       = (const float*)d_in[0];
    const float* w_emb   = (const float*)d_in[1];
    const float* b_emb   = (const float*)d_in[2];
    const float* w_atlas = (const float*)d_in[3];
    const float* b_atlas = (const float*)d_in[4];
    const float* w_k     = (const float*)d_in[5];
    const float* qn_w    = (const float*)d_in[6];
    const float* qn_b    = (const float*)d_in[7];
    const float* kn_w    = (const float*)d_in[8];
    const float* kn_b    = (const float*)d_in[9];
    const float* lq1     = (const float*)d_in[10];
    const float* lk1     = (const float*)d_in[11];
    const float* lq2     = (const float*)d_in[12];
    const float* lk2     = (const float*)d_in[13];
    float* out = (float*)d_out;

    cudaFuncSetAttribute(atlas2_kernel,
                         cudaFuncAttributeMaxDynamicSharedMemorySize, SMEM_BYTES);

    prep_kernel<<<512, 256>>>(w_emb, w_atlas, w_k);
    atlas2_kernel<<<4096, 256, SMEM_BYTES>>>(
        x, b_emb, b_atlas, qn_w, qn_b, kn_w, kn_b,
        lq1, lk1, lq2, lk2, out);
}

// round 6
// speedup vs baseline: 1.9129x; 1.2639x over previous
#include <cuda_runtime.h>
#include <math.h>

#define AA 56
#define EE 128
#define XP 134      // x e-slot pitch (ull slots), e' = e+3
#define HP 63       // h1 a-slot pitch (ull slots), odd -> conflict-free loads

typedef unsigned long long ull;

// packed weights (prep kernel fills these)
__device__ float g_w1p[8 * 56 * 56];     // [slice8][i56][g*8+t], t<7,g<7 else 0
__device__ float g_w2p[128 * 128 * 8];   // [o2][i][t(8, t<7 else 0)]
__device__ float g_wkT[128 * 128];       // [e][o]

__global__ void prep_kernel(const float* __restrict__ w_emb,
                            const float* __restrict__ w_atlas,
                            const float* __restrict__ w_k) {
    int idx = blockIdx.x * blockDim.x + threadIdx.x;
    if (idx < 8 * 56 * 56) {
        int s = idx / (56 * 56); int r = idx % (56 * 56);
        int i = r / 56; int gt = r % 56;
        int g = gt >> 3, t = gt & 7;
        float v = 0.f;
        if (t < 7 && g < 7) v = w_emb[(((s * 7 + g) * 56) + i) * 7 + t];
        g_w1p[idx] = v;
    }
    if (idx < 128 * 128 * 8) {
        int o2 = idx >> 10; int r = idx & 1023;
        int i = r >> 3, t = r & 7;
        g_w2p[idx] = (t < 7) ? w_atlas[((o2 * 128) + i) * 7 + t] : 0.f;
    }
    if (idx < 128 * 128) {
        int o = idx >> 7, e = idx & 127;
        g_wkT[e * 128 + o] = w_k[idx];
    }
}

__device__ __forceinline__ ull packf2(float v) {
    ull r; asm("mov.b64 %0,{%1,%1};" : "=l"(r) : "f"(v)); return r;
}
__device__ __forceinline__ ull pack2(float a, float b) {
    ull r; asm("mov.b64 %0,{%1,%2};" : "=l"(r) : "f"(a), "f"(b)); return r;
}
__device__ __forceinline__ void up2(ull v, float& a, float& b) {
    asm("mov.b64 {%0,%1},%2;" : "=f"(a), "=f"(b) : "l"(v));
}
__device__ __forceinline__ void fma2(ull& d, ull a, ull b) {
    asm("fma.rn.f32x2 %0,%1,%2,%0;" : "+l"(d) : "l"(a), "l"(b));
}
__device__ __forceinline__ float silu_f(float v) {
    return v / (1.f + __expf(-v));
}

// ---- x pair load: items (ib0, ib0+1) -> xs interleaved ull ----
__device__ __forceinline__ void load_x_pair(ull* xsu, const float* x, int ib0,
                                            int tid) {
    const float4* x0 = (const float4*)(x + (size_t)ib0 * AA * EE);
    const float4* x1 = (const float4*)(x + (size_t)(ib0 + 1) * AA * EE);
    for (int q = tid; q < AA * EE / 4; q += 256) {
        float4 a = x0[q], b = x1[q];
        int base = q * 4; int ar = base >> 7, e0 = base & 127;
        ull* dst = xsu + ar * XP + e0 + 3;
        dst[0] = pack2(a.x, b.x); dst[1] = pack2(a.y, b.y);
        dst[2] = pack2(a.z, b.z); dst[3] = pack2(a.w, b.w);
    }
}

// ---- conv1 for one pair-buffer ----
__device__ __forceinline__ void conv1_pass(const ull* xsu, ull* h1,
                                           const float* b_emb, int warp, int lane) {
    ull acc[7][4];
    #pragma unroll
    for (int g = 0; g < 7; g++) {
        ull b2 = packf2(b_emb[warp * 7 + g]);
        acc[g][0] = b2; acc[g][1] = b2; acc[g][2] = b2; acc[g][3] = b2;
    }
    for (int i = 0; i < AA; i++) {
        const ull* xrow = xsu + i * XP + lane;
        const float4* wrow = (const float4*)(g_w1p + (warp * 56 + i) * 56);
        ull xv[4][4];
        #pragma unroll
        for (int t = 0; t < 4; t++)
            #pragma unroll
            for (int c = 0; c < 4; c++) xv[t][c] = xrow[t + 32 * c];
        #pragma unroll
        for (int g = 0; g < 7; g++) {
            float4 wq = wrow[g * 2];
            ull w0 = packf2(wq.x), w1 = packf2(wq.y), w2 = packf2(wq.z), w3 = packf2(wq.w);
            #pragma unroll
            for (int c = 0; c < 4; c++) {
                fma2(acc[g][c], w0, xv[0][c]); fma2(acc[g][c], w1, xv[1][c]);
                fma2(acc[g][c], w2, xv[2][c]); fma2(acc[g][c], w3, xv[3][c]);
            }
        }
        #pragma unroll
        for (int t = 0; t < 3; t++)
            #pragma unroll
            for (int c = 0; c < 4; c++) xv[t][c] = xrow[4 + t + 32 * c];
        #pragma unroll
        for (int g = 0; g < 7; g++) {
            float4 wq = wrow[g * 2 + 1];
            ull w0 = packf2(wq.x), w1 = packf2(wq.y), w2 = packf2(wq.z);
            #pragma unroll
            for (int c = 0; c < 4; c++) {
                fma2(acc[g][c], w0, xv[0][c]); fma2(acc[g][c], w1, xv[1][c]);
                fma2(acc[g][c], w2, xv[2][c]);
            }
        }
    }
    #pragma unroll
    for (int g = 0; g < 7; g++)
        #pragma unroll
        for (int c = 0; c < 4; c++) {
            float v0, v1; up2(acc[g][c], v0, v1);
            float2 s = make_float2(silu_f(v0), silu_f(v1));
            *(float2*)&h1[(lane + 32 * c) * HP + (warp * 7 + g + 3)] = s;
        }
}

// ---- k-proj + LN + logits for one pair-buffer (x resident in xsu) ----
__device__ __forceinline__ void kproj_pass(const ull* xsu, const float* qnA,
                                           float* logits, int pb,
                                           const float* kn_w, const float* kn_b,
                                           int warp, int lane) {
    ull acc[7][4];
    #pragma unroll
    for (int j = 0; j < 7; j++)
        #pragma unroll
        for (int q = 0; q < 4; q++) acc[j][q] = 0ULL;
    const int p0 = warp * 7;
    for (int e = 0; e < EE; e++) {
        float4 wq = *(const float4*)(g_wkT + e * 128 + lane * 4);
        ull w0 = packf2(wq.x), w1 = packf2(wq.y), w2 = packf2(wq.z), w3 = packf2(wq.w);
        const ull* xcol = xsu + e + 3;
        #pragma unroll
        for (int j = 0; j < 7; j++) {
            ull xv = xcol[(p0 + j) * XP];
            fma2(acc[j][0], w0, xv); fma2(acc[j][1], w1, xv);
            fma2(acc[j][2], w2, xv); fma2(acc[j][3], w3, xv);
        }
    }
    float4 qv0 = *(const float4*)&qnA[(2 * pb) * 128 + lane * 4];
    float4 qv1 = *(const float4*)&qnA[(2 * pb + 1) * 128 + lane * 4];
    float4 kw = *(const float4*)(kn_w + (lane & 3) * 4);
    float4 kb = *(const float4*)(kn_b + (lane & 3) * 4);
    #pragma unroll
    for (int j = 0; j < 7; j++) {
        float k0[4], k1[4];
        #pragma unroll
        for (int q = 0; q < 4; q++) up2(acc[j][q], k0[q], k1[q]);
        #pragma unroll
        for (int itm = 0; itm < 2; itm++) {
            float* kv = itm ? k1 : k0;
            float s = kv[0] + kv[1] + kv[2] + kv[3];
            float ss = kv[0]*kv[0] + kv[1]*kv[1] + kv[2]*kv[2] + kv[3]*kv[3];
            s  += __shfl_xor_sync(0xffffffffu, s, 1);  s  += __shfl_xor_sync(0xffffffffu, s, 2);
            ss += __shfl_xor_sync(0xffffffffu, ss, 1); ss += __shfl_xor_sync(0xffffffffu, ss, 2);
            float m = s * (1.f / 16.f);
            float var = ss * (1.f / 16.f) - m * m;
            float inv = rsqrtf(var + 1e-5f);
            float4 qv = itm ? qv1 : qv0;
            float lp = ((kv[0] - m) * inv * kw.x + kb.x) * qv.x
                     + ((kv[1] - m) * inv * kw.y + kb.y) * qv.y
                     + ((kv[2] - m) * inv * kw.z + kb.z) * qv.z
                     + ((kv[3] - m) * inv * kw.w + kb.w) * qv.w;
            lp += __shfl_xor_sync(0xffffffffu, lp, 1);
            lp += __shfl_xor_sync(0xffffffffu, lp, 2);
            if ((lane & 3) == 0)
                logits[(2 * pb + itm) * 448 + (lane >> 2) * 56 + p0 + j] = lp;
        }
    }
}

__global__ __launch_bounds__(256, 1)
void atlas4_kernel(const float* __restrict__ x,
                   const float* __restrict__ b_emb,
                   const float* __restrict__ b_atlas,
                   const float* __restrict__ qn_w, const float* __restrict__ qn_b,
                   const float* __restrict__ kn_w, const float* __restrict__ kn_b,
                   const float* __restrict__ lq1, const float* __restrict__ lk1,
                   const float* __restrict__ lq2, const float* __restrict__ lk2,
                   float* __restrict__ out)
{
    extern __shared__ float sm[];
    ull*   xsu    = (ull*)sm;                       // [56*134]
    ull*   h1u    = xsu + AA * XP;                  // [2][128*63]
    float* qs     = (float*)(h1u + 2 * EE * HP);    // [4][128]
    float* qnA    = qs + 4 * 128;                   // [4][128]
    float* logits = qnA + 4 * 128;                  // [4][8][56]
    float* attn   = logits + 4 * 448;               // [4][8][56]
    float* p2     = attn + 4 * 448;                 // [4][4][56]
    float* lamp   = p2 + 4 * 224;

    const int tid = threadIdx.x, warp = tid >> 5, lane = tid & 31;
    const int bp = blockIdx.x;                      // items 4bp .. 4bp+3

    // ---- zero x + h1 buffers (halos), lambda ----
    {
        const int ZN = AA * XP + 2 * EE * HP;
        for (int i = tid; i < ZN; i += 256) xsu[i] = 0ULL;
    }
    if (tid == 0) {
        float s1 = 0.f, s2 = 0.f;
        #pragma unroll
        for (int d = 0; d < 16; d++) { s1 += lq1[d] * lk1[d]; s2 += lq2[d] * lk2[d]; }
        *lamp = __expf(s1) - __expf(s2) + 0.7f;
    }
    __syncthreads();

    // ---- conv1 for both pair-buffers (x buffer reused) ----
    load_x_pair(xsu, x, 4 * bp, tid);
    __syncthreads();
    conv1_pass(xsu, h1u, b_emb, warp, lane);
    __syncthreads();
    load_x_pair(xsu, x, 4 * bp + 2, tid);
    __syncthreads();
    conv1_pass(xsu, h1u + EE * HP, b_emb, warp, lane);
    __syncthreads();

    // ---- conv2: both pairs in one sweep, 2 passes of 8 outputs per warp ----
    #pragma unroll 1
    for (int grp = 0; grp < 2; grp++) {
        const int og0 = warp * 16 + grp * 8;
        ull acc[8][2][2];
        #pragma unroll
        for (int g = 0; g < 8; g++) {
            ull b2 = packf2(b_atlas[og0 + g]);
            acc[g][0][0] = b2; acc[g][1][0] = b2;
            acc[g][0][1] = b2; acc[g][1][1] = b2;
        }
        for (int i = 0; i < EE; i++) {
            ull hv[7][2][2];
            #pragma unroll
            for (int pb = 0; pb < 2; pb++) {
                const ull* hrow = h1u + pb * (EE * HP) + i * HP + lane;
                #pragma unroll
                for (int t = 0; t < 7; t++) {
                    hv[t][0][pb] = hrow[t];
                    hv[t][1][pb] = hrow[32 + t];
                }
            }
            const float4* wr = (const float4*)g_w2p + ((size_t)og0 * 128 + i) * 2;
            #pragma unroll
            for (int g = 0; g < 8; g++) {
                float4 wa = wr[g * 256], wb = wr[g * 256 + 1];
                ull w0 = packf2(wa.x), w1 = packf2(wa.y), w2 = packf2(wa.z), w3 = packf2(wa.w);
                ull w4 = packf2(wb.x), w5 = packf2(wb.y), w6 = packf2(wb.z);
                #pragma unroll
                for (int pb = 0; pb < 2; pb++) {
                    fma2(acc[g][0][pb], w0, hv[0][0][pb]); fma2(acc[g][1][pb], w0, hv[0][1][pb]);
                    fma2(acc[g][0][pb], w1, hv[1][0][pb]); fma2(acc[g][1][pb], w1, hv[1][1][pb]);
                    fma2(acc[g][0][pb], w2, hv[2][0][pb]); fma2(acc[g][1][pb], w2, hv[2][1][pb]);
                    fma2(acc[g][0][pb], w3, hv[3][0][pb]); fma2(acc[g][1][pb], w3, hv[3][1][pb]);
                    fma2(acc[g][0][pb], w4, hv[4][0][pb]); fma2(acc[g][1][pb], w4, hv[4][1][pb]);
                    fma2(acc[g][0][pb], w5, hv[5][0][pb]); fma2(acc[g][1][pb], w5, hv[5][1][pb]);
                    fma2(acc[g][0][pb], w6, hv[6][0][pb]); fma2(acc[g][1][pb], w6, hv[6][1][pb]);
                }
            }
        }
        #pragma unroll
        for (int g = 0; g < 8; g++) {
            #pragma unroll
            for (int pb = 0; pb < 2; pb++) {
                float a0, a1, b0, b1;
                up2(acc[g][0][pb], a0, a1);   // a-positions lane: items 2pb, 2pb+1
                up2(acc[g][1][pb], b0, b1);   // a-positions lane+32
                float s0 = silu_f(a0) + ((lane < 24) ? silu_f(b0) : 0.f);
                float s1 = silu_f(a1) + ((lane < 24) ? silu_f(b1) : 0.f);
                #pragma unroll
                for (int off = 16; off > 0; off >>= 1) {
                    s0 += __shfl_xor_sync(0xffffffffu, s0, off);
                    s1 += __shfl_xor_sync(0xffffffffu, s1, off);
                }
                if (lane == 0) {
                    qs[(2 * pb) * 128 + og0 + g]     = s0 * (1.f / 56.f);
                    qs[(2 * pb + 1) * 128 + og0 + g] = s1 * (1.f / 56.f);
                }
            }
        }
    }
    __syncthreads();

    // ---- q layernorm per head (16) + 0.25 scaling, 4 items ----
    #pragma unroll
    for (int itp = 0; itp < 2; itp++) {
        int it = itp * 2 + (tid >> 7), idx = tid & 127;
        float v = qs[it * 128 + idx];
        float s = v, ss = v * v;
        #pragma unroll
        for (int off = 8; off > 0; off >>= 1) {
            s  += __shfl_xor_sync(0xffffffffu, s,  off);
            ss += __shfl_xor_sync(0xffffffffu, ss, off);
        }
        float m = s * (1.f / 16.f);
        float var = ss * (1.f / 16.f) - m * m;
        int d = idx & 15;
        qnA[it * 128 + idx] = ((v - m) * rsqrtf(var + 1e-5f) * qn_w[d] + qn_b[d]) * 0.25f;
    }
    __syncthreads();

    // ---- k-proj: pb=1 first (x still resident), then reload pb=0 ----
    kproj_pass(xsu, qnA, logits, 1, kn_w, kn_b, warp, lane);
    __syncthreads();
    load_x_pair(xsu, x, 4 * bp, tid);
    __syncthreads();
    kproj_pass(xsu, qnA, logits, 0, kn_w, kn_b, warp, lane);
    __syncthreads();

    // ---- softmax over A per (item, h2): 8 warps, loop 4 items ----
    #pragma unroll
    for (int it = 0; it < 4; it++) {
        const float* row = logits + it * 448 + warp * 56;
        float v0 = row[lane];
        float v1 = (lane < 24) ? row[32 + lane] : -1e30f;
        float mx = fmaxf(v0, v1);
        #pragma unroll
        for (int off = 16; off > 0; off >>= 1)
            mx = fmaxf(mx, __shfl_xor_sync(0xffffffffu, mx, off));
        float e0 = __expf(v0 - mx);
        float e1 = (lane < 24) ? __expf(v1 - mx) : 0.f;
        float s = e0 + e1;
        #pragma unroll
        for (int off = 16; off > 0; off >>= 1)
            s += __shfl_xor_sync(0xffffffffu, s, off);
        float inv = 1.f / s;
        float* arow = attn + it * 448 + warp * 56;
        arow[lane] = e0 * inv;
        if (lane < 24) arow[32 + lane] = e1 * inv;
    }
    __syncthreads();

    // ---- differential combine + second softmax: 16 tasks over 8 warps ----
    #pragma unroll
    for (int itp = 0; itp < 2; itp++) {
        const int it = itp * 2 + (warp >> 2), h = warp & 3;
        const float lam = *lamp;
        const float* a0r = attn + it * 448 + (2 * h) * 56;
        const float* a1r = attn + it * 448 + (2 * h + 1) * 56;
        float v0 = a0r[lane] - lam * a1r[lane];
        float v1 = (lane < 24) ? (a0r[32 + lane] - lam * a1r[32 + lane]) : -1e30f;
        float mx = fmaxf(v0, v1);
        #pragma unroll
        for (int off = 16; off > 0; off >>= 1)
            mx = fmaxf(mx, __shfl_xor_sync(0xffffffffu, mx, off));
        float e0 = __expf(v0 - mx);
        float e1 = (lane < 24) ? __expf(v1 - mx) : 0.f;
        float s = e0 + e1;
        #pragma unroll
        for (int off = 16; off > 0; off >>= 1)
            s += __shfl_xor_sync(0xffffffffu, s, off);
        float inv = 1.f / s;
        float* prow = p2 + it * 224 + h * 56;
        prow[lane] = e0 * inv;
        if (lane < 24) prow[32 + lane] = e1 * inv;
    }
    __syncthreads();

    // ---- mean over heads, write 4 items ----
    if (tid < 224) {
        int it = tid / 56, a = tid - it * 56;
        const float* base = p2 + it * 224;
        out[(size_t)(4 * bp + it) * 56 + a] =
            0.25f * (base[a] + base[56 + a] + base[112 + a] + base[168 + a]);
    }
}

static const int SMEM_BYTES =
    (AA * XP + 2 * EE * HP) * 8 +
    (4 * 128 + 4 * 128 + 4 * 448 + 4 * 448 + 4 * 224 + 4) * 4;

extern "C" void kernel_launch(void* const* d_in, const int* in_sizes, int n_in,
                              void* d_out, int out_size) {
    const float* x       = (const float*)d_in[0];
    const float* w_emb   = (const float*)d_in[1];
    const float* b_emb   = (const float*)d_in[2];
    const float* w_atlas = (const float*)d_in[3];
    const float* b_atlas = (const float*)d_in[4];
    const float* w_k     = (const float*)d_in[5];
    const float* qn_w    = (const float*)d_in[6];
    const float* qn_b    = (const float*)d_in[7];
    const float* kn_w    = (const float*)d_in[8];
    const float* kn_b    = (const float*)d_in[9];
    const float* lq1     = (const float*)d_in[10];
    const float* lk1     = (const float*)d_in[11];
    const float* lq2     = (const float*)d_in[12];
    const float* lk2     = (const float*)d_in[13];
    float* out = (float*)d_out;

    cudaFuncSetAttribute(atlas4_kernel,
                         cudaFuncAttributeMaxDynamicSharedMemorySize, SMEM_BYTES);

    prep_kernel<<<512, 256>>>(w_emb, w_atlas, w_k);
    atlas4_kernel<<<2048, 256, SMEM_BYTES>>>(
        x, b_emb, b_atlas, qn_w, qn_b, kn_w, kn_b,
        lq1, lk1, lq2, lk2, out);
}